// round 17
// baseline (speedup 1.0000x reference)
#include <cuda_runtime.h>
#include <cuda_fp16.h>
#include <cstdint>

// out = x @ W^T (GAT attention cancels: softmax rows sum to 1; final einsum
// multiplies h by sum_j alpha = 1; adj/a_w dead).  M=8192, N=256, K=256, NT.
//
// Kernel 1: wide fp32->fp16 convert (x, W).
// Kernel 2: GEMM, TRUE software pipeline: issue chunks 0,1; then per chunk
// {wait -> sync -> issue chunk c+2 -> MMA chunk c}. 512 threads (16 warps,
// warp tile 32x16) for 2x latency hiding at same smem (96KB, 2 CTAs/SM).

#define THREADS 512
#define BM 64
#define BN 128
#define KGLOB 256
#define A_TILE_B 8192           // k-chunk A tile: 64 rows x 128B
#define B_TILE_B 16384          // k-chunk B tile: 128 rows x 128B
#define SA_BYTES (4 * A_TILE_B) // 32KB
#define SB_BYTES (4 * B_TILE_B) // 64KB
#define SMEM_TOTAL (SA_BYTES + SB_BYTES)   // 96KB -> 2 CTAs/SM

__device__ __align__(16) __half g_xh[8192 * 256];
__device__ __align__(16) __half g_wh[256 * 256];

__device__ __forceinline__ uint32_t smem_u32(const void* p) {
    uint32_t a;
    asm("{ .reg .u64 t; cvta.to.shared.u64 t, %1; cvt.u32.u64 %0, t; }" : "=r"(a) : "l"(p));
    return a;
}
__device__ __forceinline__ uint32_t swz(uint32_t off) { return off ^ ((off >> 3) & 0x70); }

__device__ __forceinline__ void cp16(uint32_t dst, const void* src) {
    asm volatile("cp.async.cg.shared.global [%0], [%1], 16;" :: "r"(dst), "l"(src) : "memory");
}
__device__ __forceinline__ void cp_commit() {
    asm volatile("cp.async.commit_group;" ::: "memory");
}
template <int N>
__device__ __forceinline__ void cp_wait() {
    asm volatile("cp.async.wait_group %0;" :: "n"(N) : "memory");
}

__device__ __forceinline__ void ldsm4(uint32_t* r, uint32_t addr) {
    asm volatile("ldmatrix.sync.aligned.m8n8.x4.shared.b16 {%0,%1,%2,%3}, [%4];"
                 : "=r"(r[0]), "=r"(r[1]), "=r"(r[2]), "=r"(r[3]) : "r"(addr));
}
__device__ __forceinline__ void ldsm2x2(uint32_t* r0, uint32_t* r1, uint32_t addr) {
    asm volatile("ldmatrix.sync.aligned.m8n8.x4.shared.b16 {%0,%1,%2,%3}, [%4];"
                 : "=r"(r0[0]), "=r"(r0[1]), "=r"(r1[0]), "=r"(r1[1]) : "r"(addr));
}
__device__ __forceinline__ void mma16816(float* c, const uint32_t* a, const uint32_t* b) {
    asm volatile("mma.sync.aligned.m16n8k16.row.col.f32.f16.f16.f32 "
                 "{%0,%1,%2,%3}, {%4,%5,%6,%7}, {%8,%9}, {%0,%1,%2,%3};"
                 : "+f"(c[0]), "+f"(c[1]), "+f"(c[2]), "+f"(c[3])
                 : "r"(a[0]), "r"(a[1]), "r"(a[2]), "r"(a[3]), "r"(b[0]), "r"(b[1]));
}
__device__ __forceinline__ uint32_t pack2(float x, float y) {
    __half2 h = __floats2half2_rn(x, y);
    return *reinterpret_cast<uint32_t*>(&h);
}

// ---------- convert x and W to fp16, wide (32 floats/thread) ----------
__global__ void __launch_bounds__(256)
cvt_all(const float4* __restrict__ x, const float4* __restrict__ w)
{
    const int b = blockIdx.x;
    const int t = threadIdx.x;
    const float4* src;
    uint4* dst;
    int outBase;
    if (b < 256) { src = x; dst = (uint4*)g_xh; outBase = b * 1024; }
    else         { src = w; dst = (uint4*)g_wh; outBase = (b - 256) * 1024; }

    float4 v[8];
#pragma unroll
    for (int i = 0; i < 4; i++) {
        int oi = outBase + t + i * 256;
        v[2 * i]     = src[2 * oi];
        v[2 * i + 1] = src[2 * oi + 1];
    }
#pragma unroll
    for (int i = 0; i < 4; i++) {
        uint4 p;
        p.x = pack2(v[2 * i].x,     v[2 * i].y);
        p.y = pack2(v[2 * i].z,     v[2 * i].w);
        p.z = pack2(v[2 * i + 1].x, v[2 * i + 1].y);
        p.w = pack2(v[2 * i + 1].z, v[2 * i + 1].w);
        dst[outBase + t + i * 256] = p;
    }
}

// ---------- GEMM: pipelined cp.async, 512 threads ----------
__global__ void __launch_bounds__(THREADS)
gat_gemm6(float* __restrict__ C)
{
    extern __shared__ __align__(1024) uint8_t smem[];
    uint8_t* sA = smem;               // 4 x 8KB
    uint8_t* sB = smem + SA_BYTES;    // 4 x 16KB

    const int tid = threadIdx.x;
    const int wid = tid >> 5;
    const int lid = tid & 31;
    const int bm = blockIdx.y, bn = blockIdx.x;
    const int wm = wid & 1;           // 2 warp rows of 32
    const int wn = wid >> 1;          // 8 warp cols of 16

    const __half* Agh = g_xh + (size_t)(bm * BM) * KGLOB;
    const __half* Bgh = g_wh + (size_t)(bn * BN) * KGLOB;

    // per-chunk cp.async: A 1/thread (64x8 slots), B 2/thread (128x8 slots)
    const int lr  = tid >> 3;         // 0..63
    const int lsl = tid & 7;
    auto issue = [&](int c) {
        uint8_t* tA = sA + c * A_TILE_B;
        cp16(smem_u32(tA + swz((uint32_t)(lr * 128 + lsl * 16))),
             Agh + (size_t)lr * KGLOB + c * 64 + lsl * 8);
        uint8_t* tB = sB + c * B_TILE_B;
#pragma unroll
        for (int i = 0; i < 2; i++) {
            int rr = lr + i * 64;
            cp16(smem_u32(tB + swz((uint32_t)(rr * 128 + lsl * 16))),
                 Bgh + (size_t)rr * KGLOB + c * 64 + lsl * 8);
        }
        cp_commit();
    };

    issue(0);
    issue(1);

    float acc[2][2][4];
#pragma unroll
    for (int i = 0; i < 2; i++)
#pragma unroll
        for (int j = 0; j < 2; j++)
#pragma unroll
            for (int k = 0; k < 4; k++) acc[i][j][k] = 0.f;

    const uint32_t a_row = (lid & 15);
    const uint32_t a_cb  = (lid >> 4) * 16;
    const uint32_t b_row = (lid & 7) + ((lid >> 4) << 3);
    const uint32_t b_cb  = ((lid >> 3) & 1) * 16;
    const uint32_t sAb = smem_u32(sA);
    const uint32_t sBb = smem_u32(sB);

    uint32_t af[2][2][4];     // [buf][mt][reg]
    uint32_t bf[2][2][2];     // [buf][nt][reg]

    auto fetch = [&](int ks, int buf) {
        const uint32_t kb = (uint32_t)(ks & 3) * 32;
        const uint32_t tA = (uint32_t)(ks >> 2) * A_TILE_B;
        const uint32_t tB = (uint32_t)(ks >> 2) * B_TILE_B;
#pragma unroll
        for (int mt = 0; mt < 2; mt++)
            ldsm4(af[buf][mt],
                  sAb + tA + swz((wm * 32 + mt * 16 + a_row) * 128 + kb + a_cb));
        ldsm2x2(bf[buf][0], bf[buf][1],
                sBb + tB + swz((wn * 16 + b_row) * 128 + kb + b_cb));
    };

#pragma unroll
    for (int c = 0; c < 4; c++) {
        if (c < 3) cp_wait<1>(); else cp_wait<0>();
        __syncthreads();              // forward-only visibility
        if (c + 2 < 4) issue(c + 2);  // overlaps with this chunk's MMA

        fetch(4 * c, 0);
#pragma unroll
        for (int ks = 0; ks < 4; ks++) {
            const int cur = ks & 1;
            if (ks < 3) fetch(4 * c + ks + 1, cur ^ 1);
#pragma unroll
            for (int mt = 0; mt < 2; mt++)
#pragma unroll
                for (int nt = 0; nt < 2; nt++)
                    mma16816(acc[mt][nt], af[cur][mt], bf[cur][nt]);
        }
    }

    // epilogue
    const int g = lid >> 2, tig = lid & 3;
#pragma unroll
    for (int mt = 0; mt < 2; mt++) {
#pragma unroll
        for (int nt = 0; nt < 2; nt++) {
            int row = bm * BM + wm * 32 + mt * 16 + g;
            int col = bn * BN + wn * 16 + nt * 8 + 2 * tig;
            *(float2*)(C + (size_t)row * 256 + col) = make_float2(acc[mt][nt][0], acc[mt][nt][1]);
            *(float2*)(C + (size_t)(row + 8) * 256 + col) = make_float2(acc[mt][nt][2], acc[mt][nt][3]);
        }
    }
}

extern "C" void kernel_launch(void* const* d_in, const int* in_sizes, int n_in,
                              void* d_out, int out_size)
{
    const float* x = (const float*)d_in[0];
    const float* W = (const float*)d_in[2];
    float* out = (float*)d_out;

    cvt_all<<<264, 256>>>((const float4*)x, (const float4*)W);

    cudaFuncSetAttribute(gat_gemm6, cudaFuncAttributeMaxDynamicSharedMemorySize, SMEM_TOTAL);
    dim3 grid(256 / BN, 8192 / BM);   // (2, 128) = 256 CTAs
    gat_gemm6<<<grid, THREADS, SMEM_TOTAL>>>(out);
}